// round 2
// baseline (speedup 1.0000x reference)
#include <cuda_runtime.h>
#include <cstdint>
#include <cstddef>

#define B_ 4
#define S_ 2048
#define E_ 1024
#define H_ 16
#define D_ 64

// Scratch for attention output (pre-projection). Static __device__ array is the
// allocation-guard-legal way to get scratch.
__device__ float g_attn[B_ * S_ * E_];

__device__ __forceinline__ unsigned f2tf32(float x) {
    unsigned u;
    asm("cvt.rna.tf32.f32 %0, %1;" : "=r"(u) : "f"(x));
    return u;
}

__device__ __forceinline__ void mma_tf32(float* d, const unsigned* a, unsigned b0, unsigned b1) {
    asm volatile(
        "mma.sync.aligned.m16n8k8.row.col.f32.tf32.tf32.f32 "
        "{%0,%1,%2,%3}, {%4,%5,%6,%7}, {%8,%9}, {%0,%1,%2,%3};\n"
        : "+f"(d[0]), "+f"(d[1]), "+f"(d[2]), "+f"(d[3])
        : "r"(a[0]), "r"(a[1]), "r"(a[2]), "r"(a[3]), "r"(b0), "r"(b1));
}

// ---------------------------------------------------------------------------
// Flash attention: one CTA = (b, h, block of 64 query rows). 4 warps, 128 thr.
// Each warp owns 16 query rows. BN = 64 keys per tile, D = 64.
// mma m16n8k8 tf32: A row-major, B col-major, C fp32.
// Fragment layout (lane: g = lane>>2, t = lane&3):
//   A: a0=(g,t) a1=(g+8,t) a2=(g,t+4) a3=(g+8,t+4)
//   B: b0=(k=t, n=g) b1=(k=t+4, n=g)
//   C: c0=(g,2t) c1=(g,2t+1) c2=(g+8,2t) c3=(g+8,2t+1)
// ---------------------------------------------------------------------------
#define LDAS 68   // smem row stride (floats): (68*g + t) % 32 == (4g+t)%32, conflict-free frag loads

__global__ void __launch_bounds__(128)
attn_kernel(const float* __restrict__ q, const float* __restrict__ k,
            const float* __restrict__ v) {
    extern __shared__ unsigned sm[];
    unsigned* Qs = sm;               // [64][68], reused as Ps after Q frags are in regs
    unsigned* Ks = sm + 64 * LDAS;   // [64][68]
    unsigned* Vs = sm + 2 * 64 * LDAS;
    unsigned* Ps = Qs;

    const int tid  = threadIdx.x;
    const int wid  = tid >> 5;
    const int lane = tid & 31;
    const int g = lane >> 2, t = lane & 3;

    const int qblk = blockIdx.x;            // 0..31
    const int h = blockIdx.y & (H_ - 1);
    const int b = blockIdx.y >> 4;

    const float scale = 0.125f;             // D^-0.5
    const size_t qbase  = ((size_t)(b * S_ + qblk * 64)) * E_ + h * D_;
    const size_t kvbase = ((size_t)(b * S_)) * E_ + h * D_;

    // Load Q tile (64x64), scale folded in, convert to tf32 bits.
    for (int i = tid; i < 64 * 16; i += 128) {
        int r = i >> 4, c = (i & 15) * 4;
        float4 f = *(const float4*)(q + qbase + (size_t)r * E_ + c);
        Qs[r * LDAS + c + 0] = f2tf32(f.x * scale);
        Qs[r * LDAS + c + 1] = f2tf32(f.y * scale);
        Qs[r * LDAS + c + 2] = f2tf32(f.z * scale);
        Qs[r * LDAS + c + 3] = f2tf32(f.w * scale);
    }
    __syncthreads();

    // Q fragments, register-resident for the whole kernel. 8 k-tiles of k=8.
    unsigned qa[8][4];
    const int r0 = 16 * wid + g;
    #pragma unroll
    for (int kk = 0; kk < 8; ++kk) {
        qa[kk][0] = Qs[r0 * LDAS + 8 * kk + t];
        qa[kk][1] = Qs[(r0 + 8) * LDAS + 8 * kk + t];
        qa[kk][2] = Qs[r0 * LDAS + 8 * kk + t + 4];
        qa[kk][3] = Qs[(r0 + 8) * LDAS + 8 * kk + t + 4];
    }

    float oacc[8][4];
    #pragma unroll
    for (int j = 0; j < 8; ++j) {
        oacc[j][0] = 0.f; oacc[j][1] = 0.f; oacc[j][2] = 0.f; oacc[j][3] = 0.f;
    }
    float m0 = -1e30f, m1 = -1e30f, l0 = 0.f, l1 = 0.f;

    for (int kt = 0; kt < S_ / 64; ++kt) {
        __syncthreads();  // prior iter's K/V (and Qs) reads done before overwrite
        const float* kp = k + kvbase + (size_t)(kt * 64) * E_;
        const float* vp = v + kvbase + (size_t)(kt * 64) * E_;
        for (int i = tid; i < 64 * 16; i += 128) {
            int r = i >> 4, c = (i & 15) * 4;
            float4 fk = *(const float4*)(kp + (size_t)r * E_ + c);
            float4 fv = *(const float4*)(vp + (size_t)r * E_ + c);
            Ks[r * LDAS + c + 0] = f2tf32(fk.x); Ks[r * LDAS + c + 1] = f2tf32(fk.y);
            Ks[r * LDAS + c + 2] = f2tf32(fk.z); Ks[r * LDAS + c + 3] = f2tf32(fk.w);
            Vs[r * LDAS + c + 0] = f2tf32(fv.x); Vs[r * LDAS + c + 1] = f2tf32(fv.y);
            Vs[r * LDAS + c + 2] = f2tf32(fv.z); Vs[r * LDAS + c + 3] = f2tf32(fv.w);
        }
        __syncthreads();

        // S = Q K^T : warp computes 16x64, j = key tile (n), kk = d tile (k)
        float sacc[8][4];
        #pragma unroll
        for (int j = 0; j < 8; ++j) {
            sacc[j][0] = 0.f; sacc[j][1] = 0.f; sacc[j][2] = 0.f; sacc[j][3] = 0.f;
        }
        #pragma unroll
        for (int kk = 0; kk < 8; ++kk) {
            #pragma unroll
            for (int j = 0; j < 8; ++j) {
                unsigned b0 = Ks[(8 * j + g) * LDAS + 8 * kk + t];
                unsigned b1 = Ks[(8 * j + g) * LDAS + 8 * kk + t + 4];
                mma_tf32(sacc[j], qa[kk], b0, b1);
            }
        }

        // Online softmax. Thread owns rows r0 (c0,c1) and r0+8 (c2,c3);
        // row is spread over the 4 lanes of a quad -> shfl_xor 1,2 reduce.
        float mx0 = -1e30f, mx1 = -1e30f;
        #pragma unroll
        for (int j = 0; j < 8; ++j) {
            mx0 = fmaxf(mx0, fmaxf(sacc[j][0], sacc[j][1]));
            mx1 = fmaxf(mx1, fmaxf(sacc[j][2], sacc[j][3]));
        }
        mx0 = fmaxf(mx0, __shfl_xor_sync(0xffffffffu, mx0, 1));
        mx0 = fmaxf(mx0, __shfl_xor_sync(0xffffffffu, mx0, 2));
        mx1 = fmaxf(mx1, __shfl_xor_sync(0xffffffffu, mx1, 1));
        mx1 = fmaxf(mx1, __shfl_xor_sync(0xffffffffu, mx1, 2));
        float mn0 = fmaxf(m0, mx0), mn1 = fmaxf(m1, mx1);
        float al0 = __expf(m0 - mn0), al1 = __expf(m1 - mn1);

        float rs0 = 0.f, rs1 = 0.f;
        #pragma unroll
        for (int j = 0; j < 8; ++j) {
            float p00 = __expf(sacc[j][0] - mn0);
            float p01 = __expf(sacc[j][1] - mn0);
            float p10 = __expf(sacc[j][2] - mn1);
            float p11 = __expf(sacc[j][3] - mn1);
            rs0 += p00 + p01; rs1 += p10 + p11;
            Ps[r0 * LDAS + 8 * j + 2 * t]       = f2tf32(p00);
            Ps[r0 * LDAS + 8 * j + 2 * t + 1]   = f2tf32(p01);
            Ps[(r0 + 8) * LDAS + 8 * j + 2 * t]     = f2tf32(p10);
            Ps[(r0 + 8) * LDAS + 8 * j + 2 * t + 1] = f2tf32(p11);
        }
        rs0 += __shfl_xor_sync(0xffffffffu, rs0, 1);
        rs0 += __shfl_xor_sync(0xffffffffu, rs0, 2);
        rs1 += __shfl_xor_sync(0xffffffffu, rs1, 1);
        rs1 += __shfl_xor_sync(0xffffffffu, rs1, 2);
        l0 = l0 * al0 + rs0;
        l1 = l1 * al1 + rs1;
        m0 = mn0; m1 = mn1;
        #pragma unroll
        for (int j = 0; j < 8; ++j) {
            oacc[j][0] *= al0; oacc[j][1] *= al0;
            oacc[j][2] *= al1; oacc[j][3] *= al1;
        }
        __syncwarp();  // Ps rows are warp-private; order writes before frag reads

        // O += P V : kk2 = key tile (k), j = d tile (n)
        #pragma unroll
        for (int kk2 = 0; kk2 < 8; ++kk2) {
            unsigned pa[4];
            pa[0] = Ps[r0 * LDAS + 8 * kk2 + t];
            pa[1] = Ps[(r0 + 8) * LDAS + 8 * kk2 + t];
            pa[2] = Ps[r0 * LDAS + 8 * kk2 + t + 4];
            pa[3] = Ps[(r0 + 8) * LDAS + 8 * kk2 + t + 4];
            #pragma unroll
            for (int j = 0; j < 8; ++j) {
                unsigned b0 = Vs[(8 * kk2 + t) * LDAS + 8 * j + g];
                unsigned b1 = Vs[(8 * kk2 + t + 4) * LDAS + 8 * j + g];
                mma_tf32(oacc[j], pa, b0, b1);
            }
        }
    }

    // Epilogue: divide by l, write to scratch.
    float inv0 = 1.0f / l0, inv1 = 1.0f / l1;
    const int grow0 = qblk * 64 + r0;
    #pragma unroll
    for (int j = 0; j < 8; ++j) {
        int c0 = h * D_ + 8 * j + 2 * t;
        float2 u0 = make_float2(oacc[j][0] * inv0, oacc[j][1] * inv0);
        float2 u1 = make_float2(oacc[j][2] * inv1, oacc[j][3] * inv1);
        *(float2*)(&g_attn[((size_t)(b * S_ + grow0)) * E_ + c0])     = u0;
        *(float2*)(&g_attn[((size_t)(b * S_ + grow0 + 8)) * E_ + c0]) = u1;
    }
}

// ---------------------------------------------------------------------------
// Output projection: C[8192,1024] = g_attn @ W^T + bias.
// CTA: 128x64 tile, 256 thr (8 warps, 4x2), warp tile 32x32, BK=32.
// ---------------------------------------------------------------------------
#define LDGP 36   // 36 % 32 == 4 -> (4g+t) frag pattern conflict-free

__global__ void __launch_bounds__(256)
proj_kernel(const float* __restrict__ W, const float* __restrict__ bias,
            float* __restrict__ C) {
    __shared__ unsigned As[128 * LDGP];
    __shared__ unsigned Ws[64 * LDGP];

    const int tid  = threadIdx.x;
    const int wid  = tid >> 5;
    const int lane = tid & 31;
    const int g = lane >> 2, t = lane & 3;
    const int wm = wid & 3, wn = wid >> 2;
    const int bm0 = blockIdx.y * 128;
    const int bn0 = blockIdx.x * 64;

    float acc[2][4][4];
    #pragma unroll
    for (int im = 0; im < 2; ++im)
        #pragma unroll
        for (int j = 0; j < 4; ++j) {
            acc[im][j][0] = 0.f; acc[im][j][1] = 0.f;
            acc[im][j][2] = 0.f; acc[im][j][3] = 0.f;
        }

    for (int kt = 0; kt < E_ / 32; ++kt) {
        __syncthreads();
        // A tile: 128 x 32
        #pragma unroll
        for (int i = tid; i < 1024; i += 256) {
            int r = i >> 3, c = (i & 7) * 4;
            float4 f = *(const float4*)(&g_attn[(size_t)(bm0 + r) * E_ + kt * 32 + c]);
            As[r * LDGP + c + 0] = f2tf32(f.x); As[r * LDGP + c + 1] = f2tf32(f.y);
            As[r * LDGP + c + 2] = f2tf32(f.z); As[r * LDGP + c + 3] = f2tf32(f.w);
        }
        // W tile: 64 x 32 (rows are output-column index n)
        #pragma unroll
        for (int i = tid; i < 512; i += 256) {
            int r = i >> 3, c = (i & 7) * 4;
            float4 f = *(const float4*)(W + (size_t)(bn0 + r) * E_ + kt * 32 + c);
            Ws[r * LDGP + c + 0] = f2tf32(f.x); Ws[r * LDGP + c + 1] = f2tf32(f.y);
            Ws[r * LDGP + c + 2] = f2tf32(f.z); Ws[r * LDGP + c + 3] = f2tf32(f.w);
        }
        __syncthreads();

        #pragma unroll
        for (int kk = 0; kk < 4; ++kk) {
            unsigned a[2][4];
            #pragma unroll
            for (int im = 0; im < 2; ++im) {
                int ar = 32 * wm + 16 * im + g;
                a[im][0] = As[ar * LDGP + 8 * kk + t];
                a[im][1] = As[(ar + 8) * LDGP + 8 * kk + t];
                a[im][2] = As[ar * LDGP + 8 * kk + t + 4];
                a[im][3] = As[(ar + 8) * LDGP + 8 * kk + t + 4];
            }
            #pragma unroll
            for (int j = 0; j < 4; ++j) {
                unsigned b0 = Ws[(32 * wn + 8 * j + g) * LDGP + 8 * kk + t];
                unsigned b1 = Ws[(32 * wn + 8 * j + g) * LDGP + 8 * kk + t + 4];
                mma_tf32(acc[0][j], a[0], b0, b1);
                mma_tf32(acc[1][j], a[1], b0, b1);
            }
        }
    }

    #pragma unroll
    for (int im = 0; im < 2; ++im) {
        int row = bm0 + 32 * wm + 16 * im + g;
        #pragma unroll
        for (int j = 0; j < 4; ++j) {
            int n0 = bn0 + 32 * wn + 8 * j + 2 * t;
            float bv0 = bias[n0], bv1 = bias[n0 + 1];
            float2 u0 = make_float2(acc[im][j][0] + bv0, acc[im][j][1] + bv1);
            float2 u1 = make_float2(acc[im][j][2] + bv0, acc[im][j][3] + bv1);
            *(float2*)(C + (size_t)row * E_ + n0)       = u0;
            *(float2*)(C + (size_t)(row + 8) * E_ + n0) = u1;
        }
    }
}

extern "C" void kernel_launch(void* const* d_in, const int* in_sizes, int n_in,
                              void* d_out, int out_size) {
    const float* q    = (const float*)d_in[0];
    const float* k    = (const float*)d_in[1];
    const float* v    = (const float*)d_in[2];
    const float* w    = (const float*)d_in[3];
    const float* bias = (const float*)d_in[4];
    float* out = (float*)d_out;

    const int attn_smem = 3 * 64 * LDAS * 4;  // 52224 bytes, needs opt-in
    cudaFuncSetAttribute(attn_kernel, cudaFuncAttributeMaxDynamicSharedMemorySize, attn_smem);

    attn_kernel<<<dim3(S_ / 64, B_ * H_), 128, attn_smem>>>(q, k, v);
    proj_kernel<<<dim3(E_ / 64, (B_ * S_) / 128), 256>>>(w, bias, out);
}

// round 4
// speedup vs baseline: 1.4788x; 1.4788x over previous
#include <cuda_runtime.h>
#include <cstdint>
#include <cstddef>

#define B_ 4
#define S_ 2048
#define E_ 1024
#define H_ 16
#define D_ 64
#define LOG2E 1.4426950408889634f

// Scratch (allocation-guard-legal): tf32-converted operands + attention output.
__device__ unsigned g_qtf[B_ * S_ * E_];
__device__ unsigned g_ktf[B_ * S_ * E_];
__device__ unsigned g_vtf[B_ * S_ * E_];
__device__ unsigned g_wtf[E_ * E_];
__device__ unsigned g_attn[B_ * S_ * E_];   // attn output, stored as tf32 bits

__device__ __forceinline__ unsigned f2tf32(float x) {
    unsigned u;
    asm("cvt.rna.tf32.f32 %0, %1;" : "=r"(u) : "f"(x));
    return u;
}
__device__ __forceinline__ float ex2f(float x) {
    float y;
    asm("ex2.approx.ftz.f32 %0, %1;" : "=f"(y) : "f"(x));
    return y;
}
__device__ __forceinline__ void mma_tf32(float* d, const unsigned* a, unsigned b0, unsigned b1) {
    asm volatile(
        "mma.sync.aligned.m16n8k8.row.col.f32.tf32.tf32.f32 "
        "{%0,%1,%2,%3}, {%4,%5,%6,%7}, {%8,%9}, {%0,%1,%2,%3};\n"
        : "+f"(d[0]), "+f"(d[1]), "+f"(d[2]), "+f"(d[3])
        : "r"(a[0]), "r"(a[1]), "r"(a[2]), "r"(a[3]), "r"(b0), "r"(b1));
}
__device__ __forceinline__ unsigned stou(const void* p) {
    unsigned a;
    asm("{ .reg .u64 tmp; cvta.to.shared.u64 tmp, %1; cvt.u32.u64 %0, tmp; }"
        : "=r"(a) : "l"(p));
    return a;
}
__device__ __forceinline__ void cp16(unsigned dst, const void* src) {
    asm volatile("cp.async.cg.shared.global [%0], [%1], 16;" :: "r"(dst), "l"(src));
}
__device__ __forceinline__ void cp_commit() { asm volatile("cp.async.commit_group;"); }
template <int N> __device__ __forceinline__ void cp_wait() {
    asm volatile("cp.async.wait_group %0;" :: "n"(N));
}

// ---------------------------------------------------------------------------
// Elementwise fp32 -> tf32-bits convert (with optional scale).
// ---------------------------------------------------------------------------
__global__ void __launch_bounds__(256)
cvt_kernel(const float* __restrict__ src, unsigned* __restrict__ dst, int n4, float scale) {
    int i = blockIdx.x * blockDim.x + threadIdx.x;
    if (i < n4) {
        float4 f = ((const float4*)src)[i];
        uint4 u;
        u.x = f2tf32(f.x * scale); u.y = f2tf32(f.y * scale);
        u.z = f2tf32(f.z * scale); u.w = f2tf32(f.w * scale);
        ((uint4*)dst)[i] = u;
    }
}

// ---------------------------------------------------------------------------
// Flash attention. CTA = (b, h, 128 q-rows), 4 warps, 32 q-rows/warp, BN=64.
// K/V double-buffered via cp.async from pre-converted tf32 arrays.
// Softmax in log2 domain (log2e folded into Q scale).
// Fragment layout (g = lane>>2, t = lane&3):
//   A: a0=(g,t) a1=(g+8,t) a2=(g,t+4) a3=(g+8,t+4)
//   B: b0=(k=t,n=g) b1=(k=t+4,n=g)
//   C: c0=(g,2t) c1=(g,2t+1) c2=(g+8,2t) c3=(g+8,2t+1)
// ---------------------------------------------------------------------------
#define LDA 68                 // stride mod 32 == 4 -> (4g+t) frag loads conflict-free
#define KV_WORDS (64 * LDA)

__global__ void __launch_bounds__(128, 2)
attn_kernel() {
    extern __shared__ unsigned sm[];
    unsigned* Qs = sm;                 // [128][LDA]; reused as Ps after frag extraction
    unsigned* KV = sm + 128 * LDA;     // 2 buffers x (K,V) each [64][LDA]

    const int tid = threadIdx.x, wid = tid >> 5, lane = tid & 31;
    const int g = lane >> 2, t = lane & 3;
    const int qblk = blockIdx.x;                  // 0..15
    const int h = blockIdx.y & (H_ - 1);
    const int b = blockIdx.y >> 4;

    const size_t qbase  = ((size_t)(b * S_ + qblk * 128)) * E_ + h * D_;
    const size_t kvbase = ((size_t)(b * S_)) * E_ + h * D_;
    const unsigned kvb = stou(sm) + 128 * LDA * 4;

    // Load Q tile (128x64), already tf32+scaled.
    #pragma unroll
    for (int n = 0; n < 16; ++n) {
        int i = tid + 128 * n;
        int r = i >> 4, c = (i & 15) * 4;
        uint4 u = *(const uint4*)(g_qtf + qbase + (size_t)r * E_ + c);
        *(uint4*)(Qs + r * LDA + c) = u;
    }
    __syncthreads();

    // Q fragments register-resident: 2 m-tiles x 8 k-slices.
    unsigned qa[2][8][4];
    const int qr = 32 * wid;
    #pragma unroll
    for (int mt = 0; mt < 2; ++mt)
        #pragma unroll
        for (int kk = 0; kk < 8; ++kk) {
            int rb = qr + 16 * mt + g;
            qa[mt][kk][0] = Qs[rb * LDA + 8 * kk + t];
            qa[mt][kk][1] = Qs[(rb + 8) * LDA + 8 * kk + t];
            qa[mt][kk][2] = Qs[rb * LDA + 8 * kk + t + 4];
            qa[mt][kk][3] = Qs[(rb + 8) * LDA + 8 * kk + t + 4];
        }

    float oacc[2][8][4] = {};
    float m[2][2], l[2][2];
    #pragma unroll
    for (int mt = 0; mt < 2; ++mt) {
        m[mt][0] = -1e30f; m[mt][1] = -1e30f;
        l[mt][0] = 0.f;    l[mt][1] = 0.f;
    }

    auto load_kv = [&](int kt, int buf) {
        const unsigned* kp = g_ktf + kvbase + (size_t)(kt * 64) * E_;
        const unsigned* vp = g_vtf + kvbase + (size_t)(kt * 64) * E_;
        unsigned kd = kvb + buf * (2 * KV_WORDS * 4);
        unsigned vd = kd + KV_WORDS * 4;
        #pragma unroll
        for (int n = 0; n < 8; ++n) {
            int i = tid + 128 * n;
            int r = i >> 4, c = (i & 15) * 4;
            cp16(kd + (r * LDA + c) * 4, kp + (size_t)r * E_ + c);
            cp16(vd + (r * LDA + c) * 4, vp + (size_t)r * E_ + c);
        }
    };

    load_kv(0, 0); cp_commit();

    for (int kt = 0; kt < S_ / 64; ++kt) {
        if (kt + 1 < S_ / 64) { load_kv(kt + 1, (kt + 1) & 1); cp_commit(); cp_wait<1>(); }
        else                  { cp_wait<0>(); }
        __syncthreads();
        const unsigned* Kb = KV + (kt & 1) * (2 * KV_WORDS);
        const unsigned* Vb = Kb + KV_WORDS;

        // S = Q K^T : 32x64 per warp
        float sacc[2][8][4] = {};
        #pragma unroll
        for (int kk = 0; kk < 8; ++kk)
            #pragma unroll
            for (int j = 0; j < 8; ++j) {
                unsigned b0 = Kb[(8 * j + g) * LDA + 8 * kk + t];
                unsigned b1 = Kb[(8 * j + g) * LDA + 8 * kk + t + 4];
                mma_tf32(sacc[0][j], qa[0][kk], b0, b1);
                mma_tf32(sacc[1][j], qa[1][kk], b0, b1);
            }

        // Online softmax (log2 domain), P written to Ps (=Qs) as tf32 bits.
        #pragma unroll
        for (int mt = 0; mt < 2; ++mt) {
            float mx0 = -1e30f, mx1 = -1e30f;
            #pragma unroll
            for (int j = 0; j < 8; ++j) {
                mx0 = fmaxf(mx0, fmaxf(sacc[mt][j][0], sacc[mt][j][1]));
                mx1 = fmaxf(mx1, fmaxf(sacc[mt][j][2], sacc[mt][j][3]));
            }
            mx0 = fmaxf(mx0, __shfl_xor_sync(0xffffffffu, mx0, 1));
            mx0 = fmaxf(mx0, __shfl_xor_sync(0xffffffffu, mx0, 2));
            mx1 = fmaxf(mx1, __shfl_xor_sync(0xffffffffu, mx1, 1));
            mx1 = fmaxf(mx1, __shfl_xor_sync(0xffffffffu, mx1, 2));
            float mn0 = fmaxf(m[mt][0], mx0), mn1 = fmaxf(m[mt][1], mx1);
            float al0 = ex2f(m[mt][0] - mn0), al1 = ex2f(m[mt][1] - mn1);

            float rs0 = 0.f, rs1 = 0.f;
            int rb0 = qr + 16 * mt + g, rb1 = rb0 + 8;
            #pragma unroll
            for (int j = 0; j < 8; ++j) {
                float p00 = ex2f(sacc[mt][j][0] - mn0);
                float p01 = ex2f(sacc[mt][j][1] - mn0);
                float p10 = ex2f(sacc[mt][j][2] - mn1);
                float p11 = ex2f(sacc[mt][j][3] - mn1);
                rs0 += p00 + p01; rs1 += p10 + p11;
                *(uint2*)(Qs + rb0 * LDA + 8 * j + 2 * t) = make_uint2(f2tf32(p00), f2tf32(p01));
                *(uint2*)(Qs + rb1 * LDA + 8 * j + 2 * t) = make_uint2(f2tf32(p10), f2tf32(p11));
            }
            rs0 += __shfl_xor_sync(0xffffffffu, rs0, 1);
            rs0 += __shfl_xor_sync(0xffffffffu, rs0, 2);
            rs1 += __shfl_xor_sync(0xffffffffu, rs1, 1);
            rs1 += __shfl_xor_sync(0xffffffffu, rs1, 2);
            l[mt][0] = l[mt][0] * al0 + rs0;
            l[mt][1] = l[mt][1] * al1 + rs1;
            m[mt][0] = mn0; m[mt][1] = mn1;
            #pragma unroll
            for (int j = 0; j < 8; ++j) {
                oacc[mt][j][0] *= al0; oacc[mt][j][1] *= al0;
                oacc[mt][j][2] *= al1; oacc[mt][j][3] *= al1;
            }
        }
        __syncwarp();   // Ps rows warp-private: order stores before frag reads

        // O += P V
        #pragma unroll
        for (int kk2 = 0; kk2 < 8; ++kk2) {
            unsigned pa[2][4];
            #pragma unroll
            for (int mt = 0; mt < 2; ++mt) {
                int rb = qr + 16 * mt + g;
                pa[mt][0] = Qs[rb * LDA + 8 * kk2 + t];
                pa[mt][1] = Qs[(rb + 8) * LDA + 8 * kk2 + t];
                pa[mt][2] = Qs[rb * LDA + 8 * kk2 + t + 4];
                pa[mt][3] = Qs[(rb + 8) * LDA + 8 * kk2 + t + 4];
            }
            #pragma unroll
            for (int j = 0; j < 8; ++j) {
                unsigned b0 = Vb[(8 * kk2 + t) * LDA + 8 * j + g];
                unsigned b1 = Vb[(8 * kk2 + t + 4) * LDA + 8 * j + g];
                mma_tf32(oacc[0][j], pa[0], b0, b1);
                mma_tf32(oacc[1][j], pa[1], b0, b1);
            }
        }
        __syncthreads();  // K/V buffer reads done before it is refilled
    }

    // Epilogue: normalize, write tf32 bits to g_attn (proj consumes directly).
    #pragma unroll
    for (int mt = 0; mt < 2; ++mt) {
        float inv0 = 1.0f / l[mt][0], inv1 = 1.0f / l[mt][1];
        int row0 = qblk * 128 + qr + 16 * mt + g;
        #pragma unroll
        for (int j = 0; j < 8; ++j) {
            int c0 = h * D_ + 8 * j + 2 * t;
            *(uint2*)(g_attn + ((size_t)(b * S_ + row0)) * E_ + c0) =
                make_uint2(f2tf32(oacc[mt][j][0] * inv0), f2tf32(oacc[mt][j][1] * inv0));
            *(uint2*)(g_attn + ((size_t)(b * S_ + row0 + 8)) * E_ + c0) =
                make_uint2(f2tf32(oacc[mt][j][2] * inv1), f2tf32(oacc[mt][j][3] * inv1));
        }
    }
}

// ---------------------------------------------------------------------------
// Output projection: C[8192,1024] = attn @ W^T + bias.
// CTA 128x128, 4 warps (2x2) of 64x64 warp tiles, BK=32, cp.async double-buffer.
// ---------------------------------------------------------------------------
#define LDP 36                // stride mod 32 == 4 -> conflict-free frag loads
#define PBUF (128 * LDP)

__global__ void __launch_bounds__(128, 2)
proj_kernel(const float* __restrict__ bias, float* __restrict__ C) {
    extern __shared__ unsigned sm[];   // [buf][A 128x36 | B 128x36]
    const int tid = threadIdx.x, wid = tid >> 5, lane = tid & 31;
    const int g = lane >> 2, t = lane & 3;
    const int wm = wid & 1, wn = wid >> 1;
    const int bm0 = blockIdx.y * 128, bn0 = blockIdx.x * 128;
    const unsigned smb = stou(sm);

    auto load_tile = [&](int kt, int buf) {
        unsigned ad = smb + buf * (2 * PBUF * 4);
        unsigned bd = ad + PBUF * 4;
        #pragma unroll
        for (int n = 0; n < 8; ++n) {
            int i = tid + 128 * n;
            int r = i >> 3, c = (i & 7) * 4;
            cp16(ad + (r * LDP + c) * 4, g_attn + (size_t)(bm0 + r) * E_ + kt * 32 + c);
            cp16(bd + (r * LDP + c) * 4, g_wtf  + (size_t)(bn0 + r) * E_ + kt * 32 + c);
        }
    };

    float acc[4][8][4] = {};
    load_tile(0, 0); cp_commit();

    for (int kt = 0; kt < E_ / 32; ++kt) {
        if (kt + 1 < E_ / 32) { load_tile(kt + 1, (kt + 1) & 1); cp_commit(); cp_wait<1>(); }
        else                  { cp_wait<0>(); }
        __syncthreads();
        const unsigned* As = sm + (kt & 1) * (2 * PBUF);
        const unsigned* Bs = As + PBUF;

        #pragma unroll
        for (int kk = 0; kk < 4; ++kk) {
            unsigned a[4][4];
            #pragma unroll
            for (int im = 0; im < 4; ++im) {
                int ar = wm * 64 + 16 * im + g;
                a[im][0] = As[ar * LDP + 8 * kk + t];
                a[im][1] = As[(ar + 8) * LDP + 8 * kk + t];
                a[im][2] = As[ar * LDP + 8 * kk + t + 4];
                a[im][3] = As[(ar + 8) * LDP + 8 * kk + t + 4];
            }
            #pragma unroll
            for (int j = 0; j < 8; ++j) {
                unsigned b0 = Bs[(wn * 64 + 8 * j + g) * LDP + 8 * kk + t];
                unsigned b1 = Bs[(wn * 64 + 8 * j + g) * LDP + 8 * kk + t + 4];
                #pragma unroll
                for (int im = 0; im < 4; ++im)
                    mma_tf32(acc[im][j], a[im], b0, b1);
            }
        }
        __syncthreads();
    }

    #pragma unroll
    for (int im = 0; im < 4; ++im) {
        int row = bm0 + wm * 64 + 16 * im + g;
        #pragma unroll
        for (int j = 0; j < 8; ++j) {
            int n0 = bn0 + wn * 64 + 8 * j + 2 * t;
            float bv0 = bias[n0], bv1 = bias[n0 + 1];
            *(float2*)(C + (size_t)row * E_ + n0) =
                make_float2(acc[im][j][0] + bv0, acc[im][j][1] + bv1);
            *(float2*)(C + (size_t)(row + 8) * E_ + n0) =
                make_float2(acc[im][j][2] + bv0, acc[im][j][3] + bv1);
        }
    }
}

extern "C" void kernel_launch(void* const* d_in, const int* in_sizes, int n_in,
                              void* d_out, int out_size) {
    const float* q    = (const float*)d_in[0];
    const float* k    = (const float*)d_in[1];
    const float* v    = (const float*)d_in[2];
    const float* w    = (const float*)d_in[3];
    const float* bias = (const float*)d_in[4];
    float* out = (float*)d_out;

    unsigned *p_qtf, *p_ktf, *p_vtf, *p_wtf;
    cudaGetSymbolAddress((void**)&p_qtf, g_qtf);
    cudaGetSymbolAddress((void**)&p_ktf, g_ktf);
    cudaGetSymbolAddress((void**)&p_vtf, g_vtf);
    cudaGetSymbolAddress((void**)&p_wtf, g_wtf);

    const int attn_smem = (128 * LDA + 4 * KV_WORDS) * 4;   // 104448
    const int proj_smem = 4 * PBUF * 4;                     // 73728
    cudaFuncSetAttribute(attn_kernel, cudaFuncAttributeMaxDynamicSharedMemorySize, attn_smem);
    cudaFuncSetAttribute(proj_kernel, cudaFuncAttributeMaxDynamicSharedMemorySize, proj_smem);

    const int NQ = B_ * S_ * E_ / 4;   // 2097152 float4s
    const int NW = E_ * E_ / 4;        // 262144
    cvt_kernel<<<NQ / 256, 256>>>(q, p_qtf, NQ, 0.125f * LOG2E);
    cvt_kernel<<<NQ / 256, 256>>>(k, p_ktf, NQ, 1.0f);
    cvt_kernel<<<NQ / 256, 256>>>(v, p_vtf, NQ, 1.0f);
    cvt_kernel<<<NW / 256, 256>>>(w, p_wtf, NW, 1.0f);

    attn_kernel<<<dim3(S_ / 128, B_ * H_), 128, attn_smem>>>();
    proj_kernel<<<dim3(E_ / 128, (B_ * S_) / 128), 128, proj_smem>>>(bias, out);
}

// round 5
// speedup vs baseline: 3.5494x; 2.4003x over previous
#include <cuda_runtime.h>
#include <cuda_fp16.h>
#include <cstdint>
#include <cstddef>

#define B_ 4
#define S_ 2048
#define E_ 1024
#define H_ 16
#define D_ 64
#define LOG2E 1.4426950408889634f

// Scratch (allocation-guard-legal): fp16-converted operands + attention output.
__device__ __half g_qh[B_ * S_ * E_];
__device__ __half g_kh[B_ * S_ * E_];
__device__ __half g_vh[B_ * S_ * E_];
__device__ __half g_wh[E_ * E_];
__device__ __half g_attn[B_ * S_ * E_];   // attn output (fp16)

__device__ __forceinline__ float ex2f(float x) {
    float y;
    asm("ex2.approx.ftz.f32 %0, %1;" : "=f"(y) : "f"(x));
    return y;
}
__device__ __forceinline__ unsigned packh2(float lo, float hi) {
    __half2 h = __floats2half2_rn(lo, hi);
    return *reinterpret_cast<unsigned*>(&h);
}
__device__ __forceinline__ void mma_f16(float* d, const unsigned* a, unsigned b0, unsigned b1) {
    asm volatile(
        "mma.sync.aligned.m16n8k16.row.col.f32.f16.f16.f32 "
        "{%0,%1,%2,%3}, {%4,%5,%6,%7}, {%8,%9}, {%0,%1,%2,%3};\n"
        : "+f"(d[0]), "+f"(d[1]), "+f"(d[2]), "+f"(d[3])
        : "r"(a[0]), "r"(a[1]), "r"(a[2]), "r"(a[3]), "r"(b0), "r"(b1));
}
__device__ __forceinline__ void ldm4(unsigned* r, unsigned addr) {
    asm volatile("ldmatrix.sync.aligned.m8n8.x4.shared.b16 {%0,%1,%2,%3}, [%4];"
        : "=r"(r[0]), "=r"(r[1]), "=r"(r[2]), "=r"(r[3]) : "r"(addr));
}
__device__ __forceinline__ void ldm4t(unsigned* r, unsigned addr) {
    asm volatile("ldmatrix.sync.aligned.m8n8.x4.trans.shared.b16 {%0,%1,%2,%3}, [%4];"
        : "=r"(r[0]), "=r"(r[1]), "=r"(r[2]), "=r"(r[3]) : "r"(addr));
}
__device__ __forceinline__ unsigned stou(const void* p) {
    unsigned a;
    asm("{ .reg .u64 tmp; cvta.to.shared.u64 tmp, %1; cvt.u32.u64 %0, tmp; }"
        : "=r"(a) : "l"(p));
    return a;
}
__device__ __forceinline__ void cp16(unsigned dst, const void* src) {
    asm volatile("cp.async.cg.shared.global [%0], [%1], 16;" :: "r"(dst), "l"(src));
}
__device__ __forceinline__ void cp_commit() { asm volatile("cp.async.commit_group;"); }
template <int N> __device__ __forceinline__ void cp_wait() {
    asm volatile("cp.async.wait_group %0;" :: "n"(N));
}

// XOR-swizzled 16B-unit offset within a tile whose rows are 64 halves (128B).
// 8 chunks/row; chunk cb of row r lives at r*8 + (cb ^ (r&7)).  ldmatrix reads
// (8 rows, fixed cb) hit 8 distinct chunk positions -> conflict-free.
__device__ __forceinline__ unsigned swz(int r, int cb) {
    return (unsigned)(r * 8 + (cb ^ (r & 7)));
}

// ---------------------------------------------------------------------------
// fp32 -> fp16 convert (with scale).
// ---------------------------------------------------------------------------
__global__ void __launch_bounds__(256)
cvt_kernel(const float* __restrict__ src, unsigned* __restrict__ dst, int n4, float scale) {
    int i = blockIdx.x * blockDim.x + threadIdx.x;
    if (i < n4) {
        float4 f = ((const float4*)src)[i];
        uint2 u;
        u.x = packh2(f.x * scale, f.y * scale);
        u.y = packh2(f.z * scale, f.w * scale);
        ((uint2*)dst)[i] = u;
    }
}

// ---------------------------------------------------------------------------
// Flash attention, fp16 mma m16n8k16. CTA = (b,h,128 q-rows), 4 warps of
// 32 q-rows, BN=64. K/V double-buffered cp.async; P stays in registers
// (QK C-frag -> PV A-frag permutation); ldmatrix for all smem frag loads.
// ---------------------------------------------------------------------------
#define QTILE_B (128 * 128)        // 128 rows x 64 halves
#define KVTILE_B (64 * 128)        // 8192 bytes per K or V tile

__global__ void __launch_bounds__(128, 2)
attn_kernel() {
    extern __shared__ __align__(16) unsigned char smraw[];
    const unsigned sb  = stou(smraw);
    const unsigned Qb  = sb;                    // 16384 B
    const unsigned KVb = sb + QTILE_B;          // 2 bufs x (K,V)

    const int tid = threadIdx.x, wid = tid >> 5, lane = tid & 31;
    const int g = lane >> 2, t = lane & 3;
    const int qblk = blockIdx.x;
    const int h = blockIdx.y & (H_ - 1);
    const int b = blockIdx.y >> 4;

    const size_t qbase  = ((size_t)(b * S_ + qblk * 128)) * E_ + h * D_;
    const size_t kvbase = ((size_t)(b * S_)) * E_ + h * D_;

    // Q tile load (128 rows x 8 chunks)
    {
        const __half* qp = g_qh + qbase;
        #pragma unroll
        for (int n = 0; n < 8; ++n) {
            int c = tid + 128 * n;
            int r = c >> 3, cb = c & 7;
            cp16(Qb + swz(r, cb) * 16, qp + (size_t)r * E_ + cb * 8);
        }
        cp_commit();
    }

    auto load_kv = [&](int kt, int buf) {
        const __half* kp = g_kh + kvbase + (size_t)(kt * 64) * E_;
        const __half* vp = g_vh + kvbase + (size_t)(kt * 64) * E_;
        unsigned kd = KVb + buf * (2 * KVTILE_B);
        unsigned vd = kd + KVTILE_B;
        #pragma unroll
        for (int n = 0; n < 4; ++n) {
            int c = tid + 128 * n;
            int r = c >> 3, cb = c & 7;
            cp16(kd + swz(r, cb) * 16, kp + (size_t)r * E_ + cb * 8);
            cp16(vd + swz(r, cb) * 16, vp + (size_t)r * E_ + cb * 8);
        }
    };
    load_kv(0, 0); cp_commit();

    // Q fragments (wait Q group only; KV0 still in flight)
    cp_wait<1>();
    __syncthreads();
    unsigned qa[2][4][4];
    const int qr = 32 * wid;
    {
        int rA = lane & 15, cA = lane >> 4;        // x4 lane pattern
        #pragma unroll
        for (int mt = 0; mt < 2; ++mt)
            #pragma unroll
            for (int kk = 0; kk < 4; ++kk)
                ldm4(qa[mt][kk], Qb + swz(qr + 16 * mt + rA, 2 * kk + cA) * 16);
    }

    float oacc[2][8][4] = {};
    float m[2][2] = {{-1e30f, -1e30f}, {-1e30f, -1e30f}};
    float l[2][2] = {{0.f, 0.f}, {0.f, 0.f}};

    // lane patterns for K (x4 non-trans B) and V (x4 trans B)
    const int rK = ((lane & 16) >> 1) + (lane & 7);   // row within 16
    const int cK = (lane >> 3) & 1;                   // 16B col half
    const int rV = lane & 15;
    const int cV = lane >> 4;

    for (int kt = 0; kt < S_ / 64; ++kt) {
        if (kt + 1 < S_ / 64) { load_kv(kt + 1, (kt + 1) & 1); cp_commit(); cp_wait<1>(); }
        else                  { cp_wait<0>(); }
        __syncthreads();
        const unsigned Kb = KVb + (kt & 1) * (2 * KVTILE_B);
        const unsigned Vb = Kb + KVTILE_B;

        // ---- S = Q K^T : 32x64 per warp ----
        float sacc[2][8][4] = {};
        #pragma unroll
        for (int jp = 0; jp < 4; ++jp) {
            unsigned kb[4][4];
            #pragma unroll
            for (int kk = 0; kk < 4; ++kk)
                ldm4(kb[kk], Kb + swz(16 * jp + rK, 2 * kk + cK) * 16);
            #pragma unroll
            for (int kk = 0; kk < 4; ++kk) {
                mma_f16(sacc[0][2 * jp],     qa[0][kk], kb[kk][0], kb[kk][1]);
                mma_f16(sacc[1][2 * jp],     qa[1][kk], kb[kk][0], kb[kk][1]);
                mma_f16(sacc[0][2 * jp + 1], qa[0][kk], kb[kk][2], kb[kk][3]);
                mma_f16(sacc[1][2 * jp + 1], qa[1][kk], kb[kk][2], kb[kk][3]);
            }
        }

        // ---- online softmax (log2 domain); P packed to fp16 A-frags ----
        unsigned pa[2][4][4];
        #pragma unroll
        for (int mt = 0; mt < 2; ++mt) {
            float mx0 = -1e30f, mx1 = -1e30f;
            #pragma unroll
            for (int j = 0; j < 8; ++j) {
                mx0 = fmaxf(mx0, fmaxf(sacc[mt][j][0], sacc[mt][j][1]));
                mx1 = fmaxf(mx1, fmaxf(sacc[mt][j][2], sacc[mt][j][3]));
            }
            mx0 = fmaxf(mx0, __shfl_xor_sync(0xffffffffu, mx0, 1));
            mx0 = fmaxf(mx0, __shfl_xor_sync(0xffffffffu, mx0, 2));
            mx1 = fmaxf(mx1, __shfl_xor_sync(0xffffffffu, mx1, 1));
            mx1 = fmaxf(mx1, __shfl_xor_sync(0xffffffffu, mx1, 2));
            float mn0 = fmaxf(m[mt][0], mx0), mn1 = fmaxf(m[mt][1], mx1);
            float al0 = ex2f(m[mt][0] - mn0), al1 = ex2f(m[mt][1] - mn1);

            float rs0 = 0.f, rs1 = 0.f;
            #pragma unroll
            for (int j = 0; j < 8; ++j) {
                float p00 = ex2f(sacc[mt][j][0] - mn0);
                float p01 = ex2f(sacc[mt][j][1] - mn0);
                float p10 = ex2f(sacc[mt][j][2] - mn1);
                float p11 = ex2f(sacc[mt][j][3] - mn1);
                rs0 += p00 + p01; rs1 += p10 + p11;
                pa[mt][j >> 1][(j & 1) * 2 + 0] = packh2(p00, p01);
                pa[mt][j >> 1][(j & 1) * 2 + 1] = packh2(p10, p11);
            }
            rs0 += __shfl_xor_sync(0xffffffffu, rs0, 1);
            rs0 += __shfl_xor_sync(0xffffffffu, rs0, 2);
            rs1 += __shfl_xor_sync(0xffffffffu, rs1, 1);
            rs1 += __shfl_xor_sync(0xffffffffu, rs1, 2);
            l[mt][0] = l[mt][0] * al0 + rs0;
            l[mt][1] = l[mt][1] * al1 + rs1;
            m[mt][0] = mn0; m[mt][1] = mn1;
            #pragma unroll
            for (int j = 0; j < 8; ++j) {
                oacc[mt][j][0] *= al0; oacc[mt][j][1] *= al0;
                oacc[mt][j][2] *= al1; oacc[mt][j][3] *= al1;
            }
        }

        // ---- O += P V (V via ldmatrix.trans) ----
        #pragma unroll
        for (int kk2 = 0; kk2 < 4; ++kk2) {
            unsigned vb[4][4];
            #pragma unroll
            for (int jp = 0; jp < 4; ++jp)
                ldm4t(vb[jp], Vb + swz(16 * kk2 + rV, 2 * jp + cV) * 16);
            #pragma unroll
            for (int jp = 0; jp < 4; ++jp) {
                mma_f16(oacc[0][2 * jp],     pa[0][kk2], vb[jp][0], vb[jp][1]);
                mma_f16(oacc[1][2 * jp],     pa[1][kk2], vb[jp][0], vb[jp][1]);
                mma_f16(oacc[0][2 * jp + 1], pa[0][kk2], vb[jp][2], vb[jp][3]);
                mma_f16(oacc[1][2 * jp + 1], pa[1][kk2], vb[jp][2], vb[jp][3]);
            }
        }
        __syncthreads();   // all reads of this KV buffer done before next refill
    }

    // epilogue: normalize, store fp16 to g_attn
    #pragma unroll
    for (int mt = 0; mt < 2; ++mt) {
        float inv0 = 1.0f / l[mt][0], inv1 = 1.0f / l[mt][1];
        int row0 = qblk * 128 + qr + 16 * mt + g;
        #pragma unroll
        for (int j = 0; j < 8; ++j) {
            int c0 = h * D_ + 8 * j + 2 * t;
            *reinterpret_cast<unsigned*>(g_attn + ((size_t)(b * S_ + row0)) * E_ + c0) =
                packh2(oacc[mt][j][0] * inv0, oacc[mt][j][1] * inv0);
            *reinterpret_cast<unsigned*>(g_attn + ((size_t)(b * S_ + row0 + 8)) * E_ + c0) =
                packh2(oacc[mt][j][2] * inv1, oacc[mt][j][3] * inv1);
        }
    }
}

// ---------------------------------------------------------------------------
// Output projection: C[8192,1024] = attn @ W^T + bias, fp16 mma.
// CTA 128x128, 4 warps (2x2) of 64x64 tiles, BK=64, double-buffered.
// ---------------------------------------------------------------------------
#define PTILE_B (128 * 128)        // 128 rows x 64 halves = 16384 B

__global__ void __launch_bounds__(128, 2)
proj_kernel(const float* __restrict__ bias, float* __restrict__ C) {
    extern __shared__ __align__(16) unsigned char smraw[];
    const unsigned sb = stou(smraw);

    const int tid = threadIdx.x, wid = tid >> 5, lane = tid & 31;
    const int g = lane >> 2, t = lane & 3;
    const int wm = wid & 1, wn = wid >> 1;
    const int bm0 = blockIdx.y * 128, bn0 = blockIdx.x * 128;

    auto load_tile = [&](int kt, int buf) {
        unsigned ad = sb + buf * (2 * PTILE_B);
        unsigned bd = ad + PTILE_B;
        #pragma unroll
        for (int n = 0; n < 8; ++n) {
            int c = tid + 128 * n;
            int r = c >> 3, cb = c & 7;
            cp16(ad + swz(r, cb) * 16, g_attn + (size_t)(bm0 + r) * E_ + kt * 64 + cb * 8);
            cp16(bd + swz(r, cb) * 16, g_wh   + (size_t)(bn0 + r) * E_ + kt * 64 + cb * 8);
        }
    };

    float acc[4][8][4] = {};
    load_tile(0, 0); cp_commit();

    const int rA = lane & 15, cA = lane >> 4;
    const int rB = ((lane & 16) >> 1) + (lane & 7), cB = (lane >> 3) & 1;

    for (int kt = 0; kt < E_ / 64; ++kt) {
        if (kt + 1 < E_ / 64) { load_tile(kt + 1, (kt + 1) & 1); cp_commit(); cp_wait<1>(); }
        else                  { cp_wait<0>(); }
        __syncthreads();
        const unsigned As = sb + (kt & 1) * (2 * PTILE_B);
        const unsigned Bs = As + PTILE_B;

        unsigned a[4][4][4];
        #pragma unroll
        for (int mt = 0; mt < 4; ++mt)
            #pragma unroll
            for (int kk = 0; kk < 4; ++kk)
                ldm4(a[mt][kk], As + swz(64 * wm + 16 * mt + rA, 2 * kk + cA) * 16);

        #pragma unroll
        for (int jp = 0; jp < 4; ++jp) {
            unsigned wb[4][4];
            #pragma unroll
            for (int kk = 0; kk < 4; ++kk)
                ldm4(wb[kk], Bs + swz(64 * wn + 16 * jp + rB, 2 * kk + cB) * 16);
            #pragma unroll
            for (int kk = 0; kk < 4; ++kk)
                #pragma unroll
                for (int mt = 0; mt < 4; ++mt) {
                    mma_f16(acc[mt][2 * jp],     a[mt][kk], wb[kk][0], wb[kk][1]);
                    mma_f16(acc[mt][2 * jp + 1], a[mt][kk], wb[kk][2], wb[kk][3]);
                }
        }
        __syncthreads();
    }

    #pragma unroll
    for (int mt = 0; mt < 4; ++mt) {
        int row = bm0 + 64 * wm + 16 * mt + g;
        #pragma unroll
        for (int j = 0; j < 8; ++j) {
            int n0 = bn0 + 64 * wn + 8 * j + 2 * t;
            float bv0 = bias[n0], bv1 = bias[n0 + 1];
            *(float2*)(C + (size_t)row * E_ + n0) =
                make_float2(acc[mt][j][0] + bv0, acc[mt][j][1] + bv1);
            *(float2*)(C + (size_t)(row + 8) * E_ + n0) =
                make_float2(acc[mt][j][2] + bv0, acc[mt][j][3] + bv1);
        }
    }
}

extern "C" void kernel_launch(void* const* d_in, const int* in_sizes, int n_in,
                              void* d_out, int out_size) {
    const float* q    = (const float*)d_in[0];
    const float* k    = (const float*)d_in[1];
    const float* v    = (const float*)d_in[2];
    const float* w    = (const float*)d_in[3];
    const float* bias = (const float*)d_in[4];
    float* out = (float*)d_out;

    void *p_q, *p_k, *p_v, *p_w;
    cudaGetSymbolAddress(&p_q, g_qh);
    cudaGetSymbolAddress(&p_k, g_kh);
    cudaGetSymbolAddress(&p_v, g_vh);
    cudaGetSymbolAddress(&p_w, g_wh);

    const int attn_smem = QTILE_B + 4 * KVTILE_B;   // 49152
    const int proj_smem = 4 * PTILE_B;              // 65536
    cudaFuncSetAttribute(attn_kernel, cudaFuncAttributeMaxDynamicSharedMemorySize, attn_smem);
    cudaFuncSetAttribute(proj_kernel, cudaFuncAttributeMaxDynamicSharedMemorySize, proj_smem);

    const int NQ = B_ * S_ * E_ / 4;
    const int NW = E_ * E_ / 4;
    cvt_kernel<<<NQ / 256, 256>>>(q, (unsigned*)p_q, NQ, 0.125f * LOG2E);
    cvt_kernel<<<NQ / 256, 256>>>(k, (unsigned*)p_k, NQ, 1.0f);
    cvt_kernel<<<NQ / 256, 256>>>(v, (unsigned*)p_v, NQ, 1.0f);
    cvt_kernel<<<NW / 256, 256>>>(w, (unsigned*)p_w, NW, 1.0f);

    attn_kernel<<<dim3(S_ / 128, B_ * H_), 128, attn_smem>>>();
    proj_kernel<<<dim3(E_ / 128, (B_ * S_) / 128), 128, proj_smem>>>(bias, out);
}